// round 16
// baseline (speedup 1.0000x reference)
#include <cuda_runtime.h>
#include <cuda_bf16.h>
#include <math.h>
#include <stdint.h>

// ---------------- scratch (device globals; no allocation allowed) ----------
__device__ float g_o1[16 * 64 * 108 * 108];   // conv1 output (pooled, NCHW)
__device__ float g_o2[16 * 128 * 52 * 52];    // conv2 output (pooled, NCHW)
__device__ float g_o3[16 * 256 * 24 * 24];    // conv3 output (pooled, NCHW)
__device__ float g_g[16 * 512];               // fc output
__device__ float g_q[16 * 448];               // attention queries (concat)
__device__ float g_s1a[16 * 11664];           // scale1 exp weights
__device__ float g_s2a[16 * 2704];            // scale2 exp weights
__device__ float g_s3a[16 * 576];             // scale3 exp weights
__device__ float g_md[6 * 16];                // per scale: [sc*32 + (m:0..15, d:16..31)]
// pre-split bf16 weights: [chunk][split(hi/lo)][oc][64ic]
__device__ __align__(256) unsigned short g_B2[25 * 2 * 128 * 64];
__device__ __align__(256) unsigned short g_B3[50 * 2 * 256 * 64];
// pre-split NHWC activations: [plane(hi/lo)][b][y][x][half][72]
__device__ __align__(256) unsigned short g_o1s[2 * 16 * 108 * 108 * 72];
__device__ __align__(256) unsigned short g_o2s[2 * 16 * 52 * 52 * 2 * 72];

// ---------------- helpers ---------------------------------------------------
__device__ __forceinline__ uint32_t smem_u32(const void* p) {
    uint32_t a;
    asm("{ .reg .u64 t; cvta.to.shared.u64 t, %1; cvt.u32.u64 %0, t; }" : "=r"(a) : "l"(p));
    return a;
}
__device__ __forceinline__ void split_bf16(float v, unsigned short& h, unsigned short& l) {
    __nv_bfloat16 hb = __float2bfloat16(v);
    float r = v - __bfloat162float(hb);
    __nv_bfloat16 lb = __float2bfloat16(r);
    h = __bfloat16_as_ushort(hb);
    l = __bfloat16_as_ushort(lb);
}
__device__ __forceinline__ unsigned long long pk_dup(float v) {
    unsigned long long r;
    asm("mov.b64 %0, {%1, %1};" : "=l"(r) : "f"(v));
    return r;
}
__device__ __forceinline__ void ffma2(unsigned long long& d,
                                      unsigned long long a, unsigned long long b) {
    asm("fma.rn.f32x2 %0, %1, %2, %0;" : "+l"(d) : "l"(a), "l"(b));
}
__device__ __forceinline__ void unpk(unsigned long long v, float& lo, float& hi) {
    asm("mov.b64 {%0, %1}, %2;" : "=f"(lo), "=f"(hi) : "l"(v));
}
__device__ __forceinline__ void cp_async16(uint32_t smem_dst, const void* gsrc) {
    asm volatile("cp.async.cg.shared.global [%0], [%1], 16;"
                 :: "r"(smem_dst), "l"(gsrc) : "memory");
}
__device__ __forceinline__ void cp_async16z(uint32_t smem_dst, const void* gsrc, int sz) {
    asm volatile("cp.async.cg.shared.global [%0], [%1], 16, %2;"
                 :: "r"(smem_dst), "l"(gsrc), "r"(sz) : "memory");
}
#define CP_COMMIT() asm volatile("cp.async.commit_group;" ::: "memory")
#define CP_WAIT0() asm volatile("cp.async.wait_group 0;" ::: "memory")
#define LDSM4(r0, r1, r2, r3, addr)                                              \
    asm volatile("ldmatrix.sync.aligned.m8n8.x4.shared.b16 {%0,%1,%2,%3}, [%4];" \
                 : "=r"(r0), "=r"(r1), "=r"(r2), "=r"(r3) : "r"(addr))
#define MMA16816(d, a, b0, b1)                                                   \
    asm volatile(                                                                \
        "mma.sync.aligned.m16n8k16.row.col.f32.bf16.bf16.f32 "                   \
        "{%0,%1,%2,%3},{%4,%5,%6,%7},{%8,%9},{%0,%1,%2,%3};"                     \
        : "+f"((d)[0]), "+f"((d)[1]), "+f"((d)[2]), "+f"((d)[3])                 \
        : "r"((a)[0]), "r"((a)[1]), "r"((a)[2]), "r"((a)[3]), "r"(b0), "r"(b1))

// ---------------- weight prep: split hi/lo bf16, [chunk][split][oc][ic64] ---
__global__ void prepB_kernel(const float* __restrict__ w, unsigned short* __restrict__ Bp,
                             int IC, int OC) {
    int i = blockIdx.x * 256 + threadIdx.x;
    int nch = (IC / 64) * 25;
    int tot = nch * OC * 64;
    if (i >= tot) return;
    int chunk = i / (OC * 64);
    int rem = i % (OC * 64);
    int oc = rem / 64;
    int ic = rem % 64;
    int half = chunk / 25;
    int k = chunk % 25;
    float v = w[((size_t)oc * IC + half * 64 + ic) * 25 + k];
    unsigned short h, l;
    split_bf16(v, h, l);
    size_t base = (size_t)chunk * 2 * OC * 64;
    Bp[base + (size_t)oc * 64 + ic] = h;
    Bp[base + (size_t)OC * 64 + (size_t)oc * 64 + ic] = l;
}

// ---------------- conv1 (IC=1) + relu + pool (FFMA2) + fused NHWC split ----
__global__ void conv1_kernel(const float* __restrict__ x, const float* __restrict__ w1,
                             const float* __restrict__ b1, float* __restrict__ o1,
                             unsigned short* __restrict__ o1s, size_t PLANE) {
    __shared__ float ism[36 * 36];
    __shared__ __align__(16) float wsm[25 * 64];  // [k][oc]
    int b = blockIdx.z;
    int ty = blockIdx.y, tx = blockIdx.x;
    int tid = threadIdx.x;

    for (int i = tid; i < 25 * 64; i += 256) {
        int oc = i & 63;
        int k = i >> 6;
        wsm[k * 64 + oc] = w1[oc * 25 + k];
    }
    int iy0 = ty * 32, ix0 = tx * 32;
    for (int i = tid; i < 36 * 36; i += 256) {
        int r = i / 36, c = i % 36;
        int gy = iy0 + r, gx = ix0 + c;
        ism[i] = (gy < 220 && gx < 220) ? x[((size_t)b * 220 + gy) * 220 + gx] : 0.f;
    }
    __syncthreads();

    int sy = tid >> 4, sx = tid & 15;
    int py = ty * 16 + sy, px = tx * 16 + sx;
    float win[36];
    int base = (sy * 2) * 36 + sx * 2;
#pragma unroll
    for (int r = 0; r < 6; r++)
#pragma unroll
        for (int c = 0; c < 6; c++) win[r * 6 + c] = ism[base + r * 36 + c];

    bool ok = (py < 108 && px < 108);
    size_t roff = (((size_t)(b * 108 + py)) * 108 + px) * 72;

#pragma unroll 1
    for (int grp = 0; grp < 4; grp++) {
        unsigned long long acc[8][4];
#pragma unroll
        for (int j = 0; j < 8; j++)
#pragma unroll
            for (int p = 0; p < 4; p++) acc[j][p] = 0ull;
#pragma unroll
        for (int ky = 0; ky < 5; ky++)
#pragma unroll
            for (int kx = 0; kx < 5; kx++) {
                unsigned long long d00 = pk_dup(win[ky * 6 + kx]);
                unsigned long long d01 = pk_dup(win[ky * 6 + kx + 1]);
                unsigned long long d10 = pk_dup(win[(ky + 1) * 6 + kx]);
                unsigned long long d11 = pk_dup(win[(ky + 1) * 6 + kx + 1]);
                const unsigned long long* wp =
                    (const unsigned long long*)&wsm[(ky * 5 + kx) * 64 + grp * 16];
#pragma unroll
                for (int j = 0; j < 8; j++) {
                    unsigned long long w = wp[j];
                    ffma2(acc[j][0], w, d00);
                    ffma2(acc[j][1], w, d01);
                    ffma2(acc[j][2], w, d10);
                    ffma2(acc[j][3], w, d11);
                }
            }
        if (ok) {
            uint32_t hw[8], lw[8];
#pragma unroll
            for (int j = 0; j < 8; j++) {
                float l0, h0, l1, h1, l2, h2, l3, h3;
                unpk(acc[j][0], l0, h0);
                unpk(acc[j][1], l1, h1);
                unpk(acc[j][2], l2, h2);
                unpk(acc[j][3], l3, h3);
                int oc = grp * 16 + j * 2;
                float vlo = fmaxf(fmaxf(l0, l1), fmaxf(l2, l3)) + b1[oc];
                float vhi = fmaxf(fmaxf(h0, h1), fmaxf(h2, h3)) + b1[oc + 1];
                vlo = fmaxf(vlo, 0.f);
                vhi = fmaxf(vhi, 0.f);
                o1[(((size_t)b * 64 + oc) * 108 + py) * 108 + px] = vlo;
                o1[(((size_t)b * 64 + oc + 1) * 108 + py) * 108 + px] = vhi;
                unsigned short hl, ll, hh, lh;
                split_bf16(vlo, hl, ll);
                split_bf16(vhi, hh, lh);
                hw[j] = (uint32_t)hl | ((uint32_t)hh << 16);
                lw[j] = (uint32_t)ll | ((uint32_t)lh << 16);
            }
            uint4* dh = (uint4*)(o1s + roff + grp * 16);
            uint4* dl = (uint4*)(o1s + PLANE + roff + grp * 16);
            dh[0] = ((const uint4*)hw)[0];
            dh[1] = ((const uint4*)hw)[1];
            dl[0] = ((const uint4*)lw)[0];
            dl[1] = ((const uint4*)lw)[1];
        }
    }
    (void)0;  // ic 64..71 pad never read by conv kernels (k16 loop covers ic<64)
}

// ---------------- mma.sync conv + relu + pool -------------------------------
// SPLITOUT: also emit pre-split NHWC bf16 planes (fused convert) — each CTA's
// ocg half maps exactly onto the [half][72] NHWC segment.
template <int IC, int OC_TOTAL, int INH, int INW, bool SPLITOUT>
__global__ void __launch_bounds__(256, 2) conv_mma_kernel(
    const unsigned short* __restrict__ ins, size_t PLANE,
    const unsigned short* __restrict__ Bp,
    const float* __restrict__ bias, float* __restrict__ out,
    unsigned short* __restrict__ outs, size_t OPLANE) {
    constexpr int OUTH = INH - 4, OUTW = INW - 4;
    constexpr int PH = OUTH / 2, PW = OUTW / 2;
    constexpr int NHALF = IC / 64;
    constexpr int NCH = NHALF * 25;
    constexpr int OCB = 64;
    constexpr int NOCG = OC_TOTAL / OCB;
    constexpr int ICPAD = 72;
    constexpr int NPOS = 240;
    constexpr int P_LO = NPOS * ICPAD * 2;
    constexpr int BS0 = 2 * P_LO;
    constexpr int BSSPLIT = OCB * ICPAD * 2;
    constexpr int BSBUF = 2 * BSSPLIT;
    constexpr int BIAS_OFF = BS0 + 2 * BSBUF;
    constexpr int NT = 256;

    extern __shared__ char smem[];
    float* bias_s = (float*)(smem + BIAS_OFF);
    uint32_t sb = smem_u32(smem);

    int tid = threadIdx.x;
    int wid = tid >> 5, lane = tid & 31;
    int wm = wid & 3, wn = wid >> 2;
    int g = lane >> 2, tg = lane & 3;

    int bz = blockIdx.z;
    int b = bz / NOCG, ocg = bz % NOCG;
    int ty = blockIdx.y, tx = blockIdx.x;

    for (int i = tid; i < OCB; i += NT) bias_s[i] = bias[ocg * OCB + i];

    int p = lane & 15;
    int khalf = ((lane >> 4) & 1) * 16;
    int arow[2];
#pragma unroll
    for (int mt = 0; mt < 2; mt++)
        arow[mt] = (wm * 4 + mt * 2 + (p >> 3)) * 12 + (p & 7);
    uint32_t brow = (uint32_t)(wn * 32 + p) * (ICPAD * 2) + khalf;

    float d[2][4][4];
#pragma unroll
    for (int mt = 0; mt < 2; mt++)
#pragma unroll
        for (int n = 0; n < 4; n++)
#pragma unroll
            for (int j = 0; j < 4; j++) d[mt][n][j] = 0.f;

    {
#pragma unroll
        for (int i = tid; i < 2 * OCB * 8; i += NT) {
            int split = i >> 9;
            int rem = i & 511;
            int oc = rem >> 3, grp = rem & 7;
            const void* src = Bp + ((size_t)split * OC_TOTAL +
                                    (size_t)(ocg * OCB + oc)) * 64 + grp * 8;
            cp_async16(sb + BS0 + split * BSSPLIT + oc * (ICPAD * 2) + grp * 16, src);
        }
        CP_COMMIT();
    }

    for (int c = 0; c < NCH; c++) {
        if (c % 25 == 0) {
            __syncthreads();
            int half = c / 25;
            for (int i = tid; i < 2 * NPOS * 9; i += NT) {
                int plane = (i >= NPOS * 9);
                int rem = plane ? i - NPOS * 9 : i;
                int pp = rem / 9, grp = rem - pp * 9;
                int r = pp / 12, cc2 = pp % 12;
                int gy = ty * 16 + r, gx = tx * 8 + cc2;
                bool ok = (gy < INH) && (gx < INW);
                size_t srcoff =
                    (((size_t)(b * INH + (ok ? gy : 0)) * INW + (ok ? gx : 0)) * NHALF +
                     half) * 72 + grp * 8;
                const void* src = ins + (size_t)plane * PLANE + srcoff;
                uint32_t dst = sb + (uint32_t)plane * P_LO + (uint32_t)(pp * 144 + grp * 16);
                cp_async16z(dst, src, ok ? 16 : 0);
            }
            CP_COMMIT();
            CP_WAIT0();
        }
        __syncthreads();

        if (c + 1 < NCH) {
            int nb = (c + 1) & 1;
            size_t gbase = (size_t)(c + 1) * 2 * OC_TOTAL * 64;
#pragma unroll
            for (int i = tid; i < 2 * OCB * 8; i += NT) {
                int split = i >> 9;
                int rem = i & 511;
                int oc = rem >> 3, grp = rem & 7;
                const void* src = Bp + gbase + ((size_t)split * OC_TOTAL +
                                                (size_t)(ocg * OCB + oc)) * 64 + grp * 8;
                cp_async16(sb + BS0 + nb * BSBUF + split * BSSPLIT + oc * (ICPAD * 2) +
                           grp * 16, src);
            }
        }
        CP_COMMIT();

        int kk = c % 25;
        int ky = kk / 5, kx = kk - ky * 5;
        uint32_t bufb = sb + BS0 + (uint32_t)((c & 1) * BSBUF);
        uint32_t aoff0 = sb + (uint32_t)(arow[0] + ky * 12 + kx) * (ICPAD * 2) + khalf;
        uint32_t aoff1 = sb + (uint32_t)(arow[1] + ky * 12 + kx) * (ICPAD * 2) + khalf;

#pragma unroll
        for (int k16 = 0; k16 < 4; k16++) {
            uint32_t koff = k16 * 32;
            uint32_t ah[2][4], al[2][4], bh[2][4], bl[2][4];
            LDSM4(ah[0][0], ah[0][1], ah[0][2], ah[0][3], aoff0 + koff);
            LDSM4(ah[1][0], ah[1][1], ah[1][2], ah[1][3], aoff1 + koff);
            LDSM4(al[0][0], al[0][1], al[0][2], al[0][3], aoff0 + P_LO + koff);
            LDSM4(al[1][0], al[1][1], al[1][2], al[1][3], aoff1 + P_LO + koff);
#pragma unroll
            for (int nb = 0; nb < 2; nb++)
                LDSM4(bh[nb][0], bh[nb][1], bh[nb][2], bh[nb][3],
                      bufb + brow + nb * 16 * (ICPAD * 2) + koff);
#pragma unroll
            for (int nb = 0; nb < 2; nb++)
                LDSM4(bl[nb][0], bl[nb][1], bl[nb][2], bl[nb][3],
                      bufb + BSSPLIT + brow + nb * 16 * (ICPAD * 2) + koff);
#pragma unroll
            for (int mt = 0; mt < 2; mt++)
#pragma unroll
                for (int n = 0; n < 4; n++)
                    MMA16816(d[mt][n], ah[mt], bh[n >> 1][n & 1], bh[n >> 1][2 + (n & 1)]);
#pragma unroll
            for (int mt = 0; mt < 2; mt++)
#pragma unroll
                for (int n = 0; n < 4; n++)
                    MMA16816(d[mt][n], al[mt], bh[n >> 1][n & 1], bh[n >> 1][2 + (n & 1)]);
#pragma unroll
            for (int mt = 0; mt < 2; mt++)
#pragma unroll
                for (int n = 0; n < 4; n++)
                    MMA16816(d[mt][n], ah[mt], bl[n >> 1][n & 1], bl[n >> 1][2 + (n & 1)]);
        }

        CP_WAIT0();
    }

    // epilogue: pool + bias + relu; optional fused split-NHWC emit
    uint32_t* hbuf = (uint32_t*)(smem + BS0);          // [32 pos][32 ocpair]
    uint32_t* lbuf = (uint32_t*)(smem + BS0 + 4096);
    if (SPLITOUT) __syncthreads();  // B buffer reads done before reuse

    bool writer = ((g & 1) == 0);
    int px = tx * 4 + (g >> 1);
#pragma unroll
    for (int mt = 0; mt < 2; mt++) {
        int py = ty * 8 + wm * 2 + mt;
#pragma unroll
        for (int n = 0; n < 4; n++) {
            float v0 = fmaxf(d[mt][n][0], d[mt][n][2]);
            float v1 = fmaxf(d[mt][n][1], d[mt][n][3]);
            v0 = fmaxf(v0, __shfl_xor_sync(~0u, v0, 4));
            v1 = fmaxf(v1, __shfl_xor_sync(~0u, v1, 4));
            if (writer) {
                int oc = wn * 32 + n * 8 + tg * 2;
                float f0 = fmaxf(v0 + bias_s[oc], 0.f);
                float f1 = fmaxf(v1 + bias_s[oc + 1], 0.f);
                if (py < PH && px < PW) {
                    int oc_g = ocg * OCB + oc;
                    size_t o0 = (((size_t)b * OC_TOTAL + oc_g) * PH + py) * PW + px;
                    out[o0] = f0;
                    out[o0 + (size_t)PH * PW] = f1;
                }
                if (SPLITOUT) {
                    unsigned short h0, l0, h1, l1;
                    split_bf16(f0, h0, l0);
                    split_bf16(f1, h1, l1);
                    int pos = (wm * 2 + mt) * 4 + (g >> 1);
                    hbuf[pos * 32 + (oc >> 1)] = (uint32_t)h0 | ((uint32_t)h1 << 16);
                    lbuf[pos * 32 + (oc >> 1)] = (uint32_t)l0 | ((uint32_t)l1 << 16);
                }
            }
        }
    }

    if (SPLITOUT) {
        __syncthreads();
        for (int i = tid; i < 512; i += NT) {
            int plane = i >> 8;
            int rem = i & 255;
            int pos = rem >> 3, grp = rem & 7;
            int ppy = pos >> 2, ppx = pos & 3;
            int py2 = ty * 8 + ppy, px2 = tx * 4 + ppx;
            if (py2 < PH && px2 < PW) {
                size_t dst = ((((size_t)(b * PH + py2)) * PW + px2) * NOCG + ocg) * 72 +
                             grp * 8;
                const uint32_t* src = (plane ? lbuf : hbuf) + pos * 32 + grp * 4;
                *(uint4*)(outs + (size_t)plane * OPLANE + dst) = *(const uint4*)src;
            }
        }
    }
}

// ---------------- fc: 4 outputs x 8 batches, grid (128,2) = 256 CTAs -------
__global__ void fc_kernel(const float* __restrict__ flat, const float* __restrict__ fcw,
                          const float* __restrict__ fcb, float* __restrict__ g) {
    constexpr int K = 256 * 24 * 24;
    int o0 = blockIdx.x * 4;
    int b0 = blockIdx.y * 8;
    int tid = threadIdx.x;
    float acc[8][4];
#pragma unroll
    for (int b = 0; b < 8; b++)
#pragma unroll
        for (int j = 0; j < 4; j++) acc[b][j] = 0.f;

    const float4* w4[4];
#pragma unroll
    for (int j = 0; j < 4; j++) w4[j] = (const float4*)(fcw + (size_t)(o0 + j) * K);

    for (int k4 = tid; k4 < K / 4; k4 += 256) {
        float4 wv[4];
#pragma unroll
        for (int j = 0; j < 4; j++) wv[j] = w4[j][k4];
#pragma unroll
        for (int b = 0; b < 8; b++) {
            float4 xv = *(const float4*)(flat + (size_t)(b0 + b) * K + (size_t)k4 * 4);
#pragma unroll
            for (int j = 0; j < 4; j++)
                acc[b][j] += wv[j].x * xv.x + wv[j].y * xv.y + wv[j].z * xv.z +
                             wv[j].w * xv.w;
        }
    }
#pragma unroll
    for (int b = 0; b < 8; b++)
#pragma unroll
        for (int j = 0; j < 4; j++)
#pragma unroll
            for (int off = 16; off; off >>= 1)
                acc[b][j] += __shfl_xor_sync(~0u, acc[b][j], off);

    __shared__ float red[8][8][4];
    int wid = tid >> 5, lid = tid & 31;
    if (lid == 0) {
#pragma unroll
        for (int b = 0; b < 8; b++)
#pragma unroll
            for (int j = 0; j < 4; j++) red[wid][b][j] = acc[b][j];
    }
    __syncthreads();
    if (tid < 32) {
        int b = tid >> 2, j = tid & 3;
        float s = fcb[o0 + j];
#pragma unroll
        for (int w = 0; w < 8; w++) s += red[w][b][j];
        g[(b0 + b) * 512 + o0 + j] = s;
    }
}

// ---------------- attention queries q[b,cc] (concat of 3 linears) ----------
__global__ void attq_kernel(const float* __restrict__ g,
                            const float* __restrict__ aw1, const float* __restrict__ ab1,
                            const float* __restrict__ aw2, const float* __restrict__ ab2,
                            const float* __restrict__ aw3, const float* __restrict__ ab3,
                            float* __restrict__ q) {
    int cc = blockIdx.x;
    int b = blockIdx.y;
    int tid = threadIdx.x;
    const float* aw;
    const float* ab;
    int c;
    if (cc < 64) { aw = aw1; ab = ab1; c = cc; }
    else if (cc < 192) { aw = aw2; ab = ab2; c = cc - 64; }
    else { aw = aw3; ab = ab3; c = cc - 192; }

    float s = 0.f;
    for (int k = tid; k < 512; k += 64) s += g[b * 512 + k] * aw[(size_t)c * 512 + k];
#pragma unroll
    for (int off = 16; off; off >>= 1) s += __shfl_xor_sync(~0u, s, off);
    __shared__ float r[2];
    if ((tid & 31) == 0) r[tid >> 5] = s;
    __syncthreads();
    if (tid == 0) q[b * 448 + cc] = r[0] + r[1] + ab[c];
}

// ---------------- merged attention scores (all 3 scales, one launch) -------
__global__ void att_scores_all(const float* __restrict__ f1, const float* __restrict__ f2,
                               const float* __restrict__ f3, const float* __restrict__ q,
                               float* __restrict__ s1, float* __restrict__ s2,
                               float* __restrict__ s3) {
    __shared__ float qs[256];
    int bx = blockIdx.x;
    int b = blockIdx.y;
    int tid = threadIdx.x;
    const float* f;
    float* s;
    int C, N, qoff, nb;
    if (bx < 46) { f = f1; s = s1; C = 64; N = 11664; qoff = 0; nb = bx; }
    else if (bx < 57) { f = f2; s = s2; C = 128; N = 2704; qoff = 64; nb = bx - 46; }
    else { f = f3; s = s3; C = 256; N = 576; qoff = 192; nb = bx - 57; }

    for (int i = tid; i < C; i += 256) qs[i] = q[b * 448 + qoff + i];
    __syncthreads();
    int n = nb * 256 + tid;
    if (n >= N) return;
    float acc = 0.f;
    for (int c = 0; c < C; c++) acc += f[((size_t)b * C + c) * N + n] * qs[c];
    s[(size_t)b * N + n] = acc;
}

// ---------------- merged softmax (48 CTAs = 3 scales x 16 batches) ---------
__global__ void att_reduce_all(float* __restrict__ s1, float* __restrict__ s2,
                               float* __restrict__ s3, float* __restrict__ md) {
    int sc = blockIdx.x >> 4;
    int b = blockIdx.x & 15;
    int tid = threadIdx.x;
    float* s;
    int N;
    if (sc == 0) { s = s1; N = 11664; }
    else if (sc == 1) { s = s2; N = 2704; }
    else { s = s3; N = 576; }

    __shared__ float sm[32];
    __shared__ float bcast;

    float mx = -1e30f;
    for (int n = tid; n < N; n += 1024) mx = fmaxf(mx, s[(size_t)b * N + n]);
#pragma unroll
    for (int off = 16; off; off >>= 1) mx = fmaxf(mx, __shfl_xor_sync(~0u, mx, off));
    if ((tid & 31) == 0) sm[tid >> 5] = mx;
    __syncthreads();
    if (tid < 32) {
        float v = sm[tid];
#pragma unroll
        for (int off = 16; off; off >>= 1) v = fmaxf(v, __shfl_xor_sync(~0u, v, off));
        if (tid == 0) bcast = v;
    }
    __syncthreads();
    float M = bcast;

    float sum = 0.f;
    for (int n = tid; n < N; n += 1024) {
        float e = expf(s[(size_t)b * N + n] - M);
        s[(size_t)b * N + n] = e;
        sum += e;
    }
#pragma unroll
    for (int off = 16; off; off >>= 1) sum += __shfl_xor_sync(~0u, sum, off);
    if ((tid & 31) == 0) sm[tid >> 5] = sum;
    __syncthreads();
    if (tid == 0) {
        float t = 0.f;
        for (int w = 0; w < 32; w++) t += sm[w];
        md[sc * 32 + b] = M;
        md[sc * 32 + 16 + b] = t;
    }
}

// ---------------- merged weighted sum (112 CTAs x 16 batches) --------------
__global__ void att_out_all(const float* __restrict__ f1, const float* __restrict__ f2,
                            const float* __restrict__ f3, const float* __restrict__ e1,
                            const float* __restrict__ e2, const float* __restrict__ e3,
                            const float* __restrict__ md, float* __restrict__ out) {
    int bx = blockIdx.x;
    int b = blockIdx.y;
    int tid = threadIdx.x;
    const float* f;
    const float* e;
    int C, N, off, c0, sc;
    if (bx < 16) { f = f1; e = e1; C = 64; N = 11664; off = 0; c0 = bx * 4; sc = 0; }
    else if (bx < 48) { f = f2; e = e2; C = 128; N = 2704; off = 64; c0 = (bx - 16) * 4; sc = 1; }
    else { f = f3; e = e3; C = 256; N = 576; off = 192; c0 = (bx - 48) * 4; sc = 2; }

    const float* er = e + (size_t)b * N;
    const float* fr = f + ((size_t)b * C + c0) * N;
    float acc[4] = {0.f, 0.f, 0.f, 0.f};
    for (int n = tid; n < N; n += 256) {
        float ev = er[n];
#pragma unroll
        for (int j = 0; j < 4; j++) acc[j] += fr[(size_t)j * N + n] * ev;
    }
#pragma unroll
    for (int j = 0; j < 4; j++)
#pragma unroll
        for (int o = 16; o; o >>= 1) acc[j] += __shfl_xor_sync(~0u, acc[j], o);
    __shared__ float sm[8][4];
    if ((tid & 31) == 0) {
#pragma unroll
        for (int j = 0; j < 4; j++) sm[tid >> 5][j] = acc[j];
    }
    __syncthreads();
    if (tid < 4) {
        float t = 0.f;
#pragma unroll
        for (int w = 0; w < 8; w++) t += sm[w][tid];
        out[b * 448 + off + c0 + tid] = t / md[sc * 32 + 16 + b];
    }
}

// ---------------- launch ----------------------------------------------------
extern "C" void kernel_launch(void* const* d_in, const int* in_sizes, int n_in,
                              void* d_out, int out_size) {
    const float* x = (const float*)d_in[0];
    const float* w1 = (const float*)d_in[1];
    const float* b1 = (const float*)d_in[2];
    const float* w2 = (const float*)d_in[3];
    const float* b2 = (const float*)d_in[4];
    const float* w3 = (const float*)d_in[5];
    const float* b3 = (const float*)d_in[6];
    const float* fcw = (const float*)d_in[7];
    const float* fcb = (const float*)d_in[8];
    const float* aw1 = (const float*)d_in[9];
    const float* ab1 = (const float*)d_in[10];
    const float* aw2 = (const float*)d_in[11];
    const float* ab2 = (const float*)d_in[12];
    const float* aw3 = (const float*)d_in[13];
    const float* ab3 = (const float*)d_in[14];
    float* out = (float*)d_out;

    float *o1, *o2, *o3, *gg, *qq, *s1b, *s2b, *s3b, *md;
    unsigned short *B2, *B3, *o1s, *o2s;
    cudaGetSymbolAddress((void**)&o1, g_o1);
    cudaGetSymbolAddress((void**)&o2, g_o2);
    cudaGetSymbolAddress((void**)&o3, g_o3);
    cudaGetSymbolAddress((void**)&gg, g_g);
    cudaGetSymbolAddress((void**)&qq, g_q);
    cudaGetSymbolAddress((void**)&s1b, g_s1a);
    cudaGetSymbolAddress((void**)&s2b, g_s2a);
    cudaGetSymbolAddress((void**)&s3b, g_s3a);
    cudaGetSymbolAddress((void**)&md, g_md);
    cudaGetSymbolAddress((void**)&B2, g_B2);
    cudaGetSymbolAddress((void**)&B3, g_B3);
    cudaGetSymbolAddress((void**)&o1s, g_o1s);
    cudaGetSymbolAddress((void**)&o2s, g_o2s);

    const size_t PLANE1 = (size_t)16 * 108 * 108 * 72;
    const size_t PLANE2 = (size_t)16 * 52 * 52 * 2 * 72;

    const int SMEM = 69120 + 36864 + 256;
    cudaFuncSetAttribute((const void*)conv_mma_kernel<64, 128, 108, 108, true>,
                         cudaFuncAttributeMaxDynamicSharedMemorySize, SMEM);
    cudaFuncSetAttribute((const void*)conv_mma_kernel<128, 256, 52, 52, false>,
                         cudaFuncAttributeMaxDynamicSharedMemorySize, SMEM);

    prepB_kernel<<<(25 * 128 * 64 + 255) / 256, 256>>>(w2, B2, 64, 128);
    prepB_kernel<<<(50 * 256 * 64 + 255) / 256, 256>>>(w3, B3, 128, 256);

    conv1_kernel<<<dim3(7, 7, 16), 256>>>(x, w1, b1, o1, o1s, PLANE1);
    // conv2 writes fp32 NCHW o2 AND pre-split NHWC o2s (convert2 fused away)
    conv_mma_kernel<64, 128, 108, 108, true><<<dim3(13, 7, 32), 256, SMEM>>>(
        o1s, PLANE1, B2, b2, o2, o2s, PLANE2);
    conv_mma_kernel<128, 256, 52, 52, false><<<dim3(6, 3, 64), 256, SMEM>>>(
        o2s, PLANE2, B3, b3, o3, nullptr, 0);

    fc_kernel<<<dim3(128, 2), 256>>>(o3, fcw, fcb, gg);
    attq_kernel<<<dim3(448, 16), 64>>>(gg, aw1, ab1, aw2, ab2, aw3, ab3, qq);

    // merged attention: all 3 scales concurrent within each launch
    att_scores_all<<<dim3(60, 16), 256>>>(o1, o2, o3, qq, s1b, s2b, s3b);
    att_reduce_all<<<48, 1024>>>(s1b, s2b, s3b, md);
    att_out_all<<<dim3(112, 16), 256>>>(o1, o2, o3, s1b, s2b, s3b, md, out);
}

// round 17
// speedup vs baseline: 1.0274x; 1.0274x over previous
#include <cuda_runtime.h>
#include <cuda_bf16.h>
#include <math.h>
#include <stdint.h>

// ---------------- scratch (device globals; no allocation allowed) ----------
__device__ float g_o1[16 * 64 * 108 * 108];   // conv1 output (pooled, NCHW)
__device__ float g_o2[16 * 128 * 52 * 52];    // conv2 output (pooled, NCHW)
__device__ float g_o3[16 * 256 * 24 * 24];    // conv3 output (pooled, NCHW)
__device__ float g_g[16 * 512];               // fc output
__device__ float g_q[16 * 448];               // attention queries (concat)
__device__ float g_s1a[16 * 11664];           // scale1 exp weights
__device__ float g_s2a[16 * 2704];            // scale2 exp weights
__device__ float g_s3a[16 * 576];             // scale3 exp weights
__device__ float g_md[6 * 16];                // per scale: [sc*32 + (m:0..15, d:16..31)]
// pre-split bf16 weights: [chunk][split(hi/lo)][oc][64ic]
__device__ __align__(256) unsigned short g_B2[25 * 2 * 128 * 64];
__device__ __align__(256) unsigned short g_B3[50 * 2 * 256 * 64];
// pre-split NHWC activations: [plane(hi/lo)][b][y][x][half][72]
__device__ __align__(256) unsigned short g_o1s[2 * 16 * 108 * 108 * 72];
__device__ __align__(256) unsigned short g_o2s[2 * 16 * 52 * 52 * 2 * 72];

// ---------------- helpers ---------------------------------------------------
__device__ __forceinline__ uint32_t smem_u32(const void* p) {
    uint32_t a;
    asm("{ .reg .u64 t; cvta.to.shared.u64 t, %1; cvt.u32.u64 %0, t; }" : "=r"(a) : "l"(p));
    return a;
}
__device__ __forceinline__ void split_bf16(float v, unsigned short& h, unsigned short& l) {
    __nv_bfloat16 hb = __float2bfloat16(v);
    float r = v - __bfloat162float(hb);
    __nv_bfloat16 lb = __float2bfloat16(r);
    h = __bfloat16_as_ushort(hb);
    l = __bfloat16_as_ushort(lb);
}
__device__ __forceinline__ unsigned long long pk_dup(float v) {
    unsigned long long r;
    asm("mov.b64 %0, {%1, %1};" : "=l"(r) : "f"(v));
    return r;
}
__device__ __forceinline__ void ffma2(unsigned long long& d,
                                      unsigned long long a, unsigned long long b) {
    asm("fma.rn.f32x2 %0, %1, %2, %0;" : "+l"(d) : "l"(a), "l"(b));
}
__device__ __forceinline__ void unpk(unsigned long long v, float& lo, float& hi) {
    asm("mov.b64 {%0, %1}, %2;" : "=f"(lo), "=f"(hi) : "l"(v));
}
__device__ __forceinline__ void cp_async16(uint32_t smem_dst, const void* gsrc) {
    asm volatile("cp.async.cg.shared.global [%0], [%1], 16;"
                 :: "r"(smem_dst), "l"(gsrc) : "memory");
}
__device__ __forceinline__ void cp_async16z(uint32_t smem_dst, const void* gsrc, int sz) {
    asm volatile("cp.async.cg.shared.global [%0], [%1], 16, %2;"
                 :: "r"(smem_dst), "l"(gsrc), "r"(sz) : "memory");
}
#define CP_COMMIT() asm volatile("cp.async.commit_group;" ::: "memory")
#define CP_WAIT0() asm volatile("cp.async.wait_group 0;" ::: "memory")
#define LDSM4(r0, r1, r2, r3, addr)                                              \
    asm volatile("ldmatrix.sync.aligned.m8n8.x4.shared.b16 {%0,%1,%2,%3}, [%4];" \
                 : "=r"(r0), "=r"(r1), "=r"(r2), "=r"(r3) : "r"(addr))
#define MMA16816(d, a, b0, b1)                                                   \
    asm volatile(                                                                \
        "mma.sync.aligned.m16n8k16.row.col.f32.bf16.bf16.f32 "                   \
        "{%0,%1,%2,%3},{%4,%5,%6,%7},{%8,%9},{%0,%1,%2,%3};"                     \
        : "+f"((d)[0]), "+f"((d)[1]), "+f"((d)[2]), "+f"((d)[3])                 \
        : "r"((a)[0]), "r"((a)[1]), "r"((a)[2]), "r"((a)[3]), "r"(b0), "r"(b1))

// ---------------- weight prep: split hi/lo bf16, [chunk][split][oc][ic64] ---
__global__ void prepB_kernel(const float* __restrict__ w, unsigned short* __restrict__ Bp,
                             int IC, int OC) {
    int i = blockIdx.x * 256 + threadIdx.x;
    int nch = (IC / 64) * 25;
    int tot = nch * OC * 64;
    if (i >= tot) return;
    int chunk = i / (OC * 64);
    int rem = i % (OC * 64);
    int oc = rem / 64;
    int ic = rem % 64;
    int half = chunk / 25;
    int k = chunk % 25;
    float v = w[((size_t)oc * IC + half * 64 + ic) * 25 + k];
    unsigned short h, l;
    split_bf16(v, h, l);
    size_t base = (size_t)chunk * 2 * OC * 64;
    Bp[base + (size_t)oc * 64 + ic] = h;
    Bp[base + (size_t)OC * 64 + (size_t)oc * 64 + ic] = l;
}

// ---------------- conv1 (IC=1) + relu + pool (FFMA2) + fused NHWC split ----
__global__ void conv1_kernel(const float* __restrict__ x, const float* __restrict__ w1,
                             const float* __restrict__ b1, float* __restrict__ o1,
                             unsigned short* __restrict__ o1s, size_t PLANE) {
    __shared__ float ism[36 * 36];
    __shared__ __align__(16) float wsm[25 * 64];  // [k][oc]
    int b = blockIdx.z;
    int ty = blockIdx.y, tx = blockIdx.x;
    int tid = threadIdx.x;

    for (int i = tid; i < 25 * 64; i += 256) {
        int oc = i & 63;
        int k = i >> 6;
        wsm[k * 64 + oc] = w1[oc * 25 + k];
    }
    int iy0 = ty * 32, ix0 = tx * 32;
    for (int i = tid; i < 36 * 36; i += 256) {
        int r = i / 36, c = i % 36;
        int gy = iy0 + r, gx = ix0 + c;
        ism[i] = (gy < 220 && gx < 220) ? x[((size_t)b * 220 + gy) * 220 + gx] : 0.f;
    }
    __syncthreads();

    int sy = tid >> 4, sx = tid & 15;
    int py = ty * 16 + sy, px = tx * 16 + sx;
    float win[36];
    int base = (sy * 2) * 36 + sx * 2;
#pragma unroll
    for (int r = 0; r < 6; r++)
#pragma unroll
        for (int c = 0; c < 6; c++) win[r * 6 + c] = ism[base + r * 36 + c];

    bool ok = (py < 108 && px < 108);
    size_t roff = (((size_t)(b * 108 + py)) * 108 + px) * 72;

#pragma unroll 1
    for (int grp = 0; grp < 4; grp++) {
        unsigned long long acc[8][4];
#pragma unroll
        for (int j = 0; j < 8; j++)
#pragma unroll
            for (int p = 0; p < 4; p++) acc[j][p] = 0ull;
#pragma unroll
        for (int ky = 0; ky < 5; ky++)
#pragma unroll
            for (int kx = 0; kx < 5; kx++) {
                unsigned long long d00 = pk_dup(win[ky * 6 + kx]);
                unsigned long long d01 = pk_dup(win[ky * 6 + kx + 1]);
                unsigned long long d10 = pk_dup(win[(ky + 1) * 6 + kx]);
                unsigned long long d11 = pk_dup(win[(ky + 1) * 6 + kx + 1]);
                const unsigned long long* wp =
                    (const unsigned long long*)&wsm[(ky * 5 + kx) * 64 + grp * 16];
#pragma unroll
                for (int j = 0; j < 8; j++) {
                    unsigned long long w = wp[j];
                    ffma2(acc[j][0], w, d00);
                    ffma2(acc[j][1], w, d01);
                    ffma2(acc[j][2], w, d10);
                    ffma2(acc[j][3], w, d11);
                }
            }
        if (ok) {
            uint32_t hw[8], lw[8];
#pragma unroll
            for (int j = 0; j < 8; j++) {
                float l0, h0, l1, h1, l2, h2, l3, h3;
                unpk(acc[j][0], l0, h0);
                unpk(acc[j][1], l1, h1);
                unpk(acc[j][2], l2, h2);
                unpk(acc[j][3], l3, h3);
                int oc = grp * 16 + j * 2;
                float vlo = fmaxf(fmaxf(l0, l1), fmaxf(l2, l3)) + b1[oc];
                float vhi = fmaxf(fmaxf(h0, h1), fmaxf(h2, h3)) + b1[oc + 1];
                vlo = fmaxf(vlo, 0.f);
                vhi = fmaxf(vhi, 0.f);
                o1[(((size_t)b * 64 + oc) * 108 + py) * 108 + px] = vlo;
                o1[(((size_t)b * 64 + oc + 1) * 108 + py) * 108 + px] = vhi;
                unsigned short hl, ll, hh, lh;
                split_bf16(vlo, hl, ll);
                split_bf16(vhi, hh, lh);
                hw[j] = (uint32_t)hl | ((uint32_t)hh << 16);
                lw[j] = (uint32_t)ll | ((uint32_t)lh << 16);
            }
            uint4* dh = (uint4*)(o1s + roff + grp * 16);
            uint4* dl = (uint4*)(o1s + PLANE + roff + grp * 16);
            dh[0] = ((const uint4*)hw)[0];
            dh[1] = ((const uint4*)hw)[1];
            dl[0] = ((const uint4*)lw)[0];
            dl[1] = ((const uint4*)lw)[1];
        }
    }
}

// ---------------- mma.sync conv + relu + pool -------------------------------
// SPLITOUT: also emit pre-split NHWC bf16 planes (fused convert).
template <int IC, int OC_TOTAL, int INH, int INW, bool SPLITOUT>
__global__ void __launch_bounds__(256, 2) conv_mma_kernel(
    const unsigned short* __restrict__ ins, size_t PLANE,
    const unsigned short* __restrict__ Bp,
    const float* __restrict__ bias, float* __restrict__ out,
    unsigned short* __restrict__ outs, size_t OPLANE) {
    constexpr int OUTH = INH - 4, OUTW = INW - 4;
    constexpr int PH = OUTH / 2, PW = OUTW / 2;
    constexpr int NHALF = IC / 64;
    constexpr int NCH = NHALF * 25;
    constexpr int OCB = 64;
    constexpr int NOCG = OC_TOTAL / OCB;
    constexpr int ICPAD = 72;
    constexpr int NPOS = 240;
    constexpr int P_LO = NPOS * ICPAD * 2;
    constexpr int BS0 = 2 * P_LO;
    constexpr int BSSPLIT = OCB * ICPAD * 2;
    constexpr int BSBUF = 2 * BSSPLIT;
    constexpr int BIAS_OFF = BS0 + 2 * BSBUF;
    constexpr int NT = 256;

    extern __shared__ char smem[];
    float* bias_s = (float*)(smem + BIAS_OFF);
    uint32_t sb = smem_u32(smem);

    int tid = threadIdx.x;
    int wid = tid >> 5, lane = tid & 31;
    int wm = wid & 3, wn = wid >> 2;
    int g = lane >> 2, tg = lane & 3;

    int bz = blockIdx.z;
    int b = bz / NOCG, ocg = bz % NOCG;
    int ty = blockIdx.y, tx = blockIdx.x;

    for (int i = tid; i < OCB; i += NT) bias_s[i] = bias[ocg * OCB + i];

    int p = lane & 15;
    int khalf = ((lane >> 4) & 1) * 16;
    int arow[2];
#pragma unroll
    for (int mt = 0; mt < 2; mt++)
        arow[mt] = (wm * 4 + mt * 2 + (p >> 3)) * 12 + (p & 7);
    uint32_t brow = (uint32_t)(wn * 32 + p) * (ICPAD * 2) + khalf;

    float d[2][4][4];
#pragma unroll
    for (int mt = 0; mt < 2; mt++)
#pragma unroll
        for (int n = 0; n < 4; n++)
#pragma unroll
            for (int j = 0; j < 4; j++) d[mt][n][j] = 0.f;

    {
#pragma unroll
        for (int i = tid; i < 2 * OCB * 8; i += NT) {
            int split = i >> 9;
            int rem = i & 511;
            int oc = rem >> 3, grp = rem & 7;
            const void* src = Bp + ((size_t)split * OC_TOTAL +
                                    (size_t)(ocg * OCB + oc)) * 64 + grp * 8;
            cp_async16(sb + BS0 + split * BSSPLIT + oc * (ICPAD * 2) + grp * 16, src);
        }
        CP_COMMIT();
    }

    for (int c = 0; c < NCH; c++) {
        if (c % 25 == 0) {
            __syncthreads();
            int half = c / 25;
            for (int i = tid; i < 2 * NPOS * 9; i += NT) {
                int plane = (i >= NPOS * 9);
                int rem = plane ? i - NPOS * 9 : i;
                int pp = rem / 9, grp = rem - pp * 9;
                int r = pp / 12, cc2 = pp % 12;
                int gy = ty * 16 + r, gx = tx * 8 + cc2;
                bool ok = (gy < INH) && (gx < INW);
                size_t srcoff =
                    (((size_t)(b * INH + (ok ? gy : 0)) * INW + (ok ? gx : 0)) * NHALF +
                     half) * 72 + grp * 8;
                const void* src = ins + (size_t)plane * PLANE + srcoff;
                uint32_t dst = sb + (uint32_t)plane * P_LO + (uint32_t)(pp * 144 + grp * 16);
                cp_async16z(dst, src, ok ? 16 : 0);
            }
            CP_COMMIT();
            CP_WAIT0();
        }
        __syncthreads();

        if (c + 1 < NCH) {
            int nb = (c + 1) & 1;
            size_t gbase = (size_t)(c + 1) * 2 * OC_TOTAL * 64;
#pragma unroll
            for (int i = tid; i < 2 * OCB * 8; i += NT) {
                int split = i >> 9;
                int rem = i & 511;
                int oc = rem >> 3, grp = rem & 7;
                const void* src = Bp + gbase + ((size_t)split * OC_TOTAL +
                                                (size_t)(ocg * OCB + oc)) * 64 + grp * 8;
                cp_async16(sb + BS0 + nb * BSBUF + split * BSSPLIT + oc * (ICPAD * 2) +
                           grp * 16, src);
            }
        }
        CP_COMMIT();

        int kk = c % 25;
        int ky = kk / 5, kx = kk - ky * 5;
        uint32_t bufb = sb + BS0 + (uint32_t)((c & 1) * BSBUF);
        uint32_t aoff0 = sb + (uint32_t)(arow[0] + ky * 12 + kx) * (ICPAD * 2) + khalf;
        uint32_t aoff1 = sb + (uint32_t)(arow[1] + ky * 12 + kx) * (ICPAD * 2) + khalf;

#pragma unroll
        for (int k16 = 0; k16 < 4; k16++) {
            uint32_t koff = k16 * 32;
            uint32_t ah[2][4], al[2][4], bh[2][4], bl[2][4];
            LDSM4(ah[0][0], ah[0][1], ah[0][2], ah[0][3], aoff0 + koff);
            LDSM4(ah[1][0], ah[1][1], ah[1][2], ah[1][3], aoff1 + koff);
            LDSM4(al[0][0], al[0][1], al[0][2], al[0][3], aoff0 + P_LO + koff);
            LDSM4(al[1][0], al[1][1], al[1][2], al[1][3], aoff1 + P_LO + koff);
#pragma unroll
            for (int nb = 0; nb < 2; nb++)
                LDSM4(bh[nb][0], bh[nb][1], bh[nb][2], bh[nb][3],
                      bufb + brow + nb * 16 * (ICPAD * 2) + koff);
#pragma unroll
            for (int nb = 0; nb < 2; nb++)
                LDSM4(bl[nb][0], bl[nb][1], bl[nb][2], bl[nb][3],
                      bufb + BSSPLIT + brow + nb * 16 * (ICPAD * 2) + koff);
#pragma unroll
            for (int mt = 0; mt < 2; mt++)
#pragma unroll
                for (int n = 0; n < 4; n++)
                    MMA16816(d[mt][n], ah[mt], bh[n >> 1][n & 1], bh[n >> 1][2 + (n & 1)]);
#pragma unroll
            for (int mt = 0; mt < 2; mt++)
#pragma unroll
                for (int n = 0; n < 4; n++)
                    MMA16816(d[mt][n], al[mt], bh[n >> 1][n & 1], bh[n >> 1][2 + (n & 1)]);
#pragma unroll
            for (int mt = 0; mt < 2; mt++)
#pragma unroll
                for (int n = 0; n < 4; n++)
                    MMA16816(d[mt][n], ah[mt], bl[n >> 1][n & 1], bl[n >> 1][2 + (n & 1)]);
        }

        CP_WAIT0();
    }

    // epilogue: pool + bias + relu; optional fused split-NHWC emit
    uint32_t* hbuf = (uint32_t*)(smem + BS0);
    uint32_t* lbuf = (uint32_t*)(smem + BS0 + 4096);
    if (SPLITOUT) __syncthreads();

    bool writer = ((g & 1) == 0);
    int px = tx * 4 + (g >> 1);
#pragma unroll
    for (int mt = 0; mt < 2; mt++) {
        int py = ty * 8 + wm * 2 + mt;
#pragma unroll
        for (int n = 0; n < 4; n++) {
            float v0 = fmaxf(d[mt][n][0], d[mt][n][2]);
            float v1 = fmaxf(d[mt][n][1], d[mt][n][3]);
            v0 = fmaxf(v0, __shfl_xor_sync(~0u, v0, 4));
            v1 = fmaxf(v1, __shfl_xor_sync(~0u, v1, 4));
            if (writer) {
                int oc = wn * 32 + n * 8 + tg * 2;
                float f0 = fmaxf(v0 + bias_s[oc], 0.f);
                float f1 = fmaxf(v1 + bias_s[oc + 1], 0.f);
                if (py < PH && px < PW) {
                    int oc_g = ocg * OCB + oc;
                    size_t o0 = (((size_t)b * OC_TOTAL + oc_g) * PH + py) * PW + px;
                    out[o0] = f0;
                    out[o0 + (size_t)PH * PW] = f1;
                }
                if (SPLITOUT) {
                    unsigned short h0, l0, h1, l1;
                    split_bf16(f0, h0, l0);
                    split_bf16(f1, h1, l1);
                    int pos = (wm * 2 + mt) * 4 + (g >> 1);
                    hbuf[pos * 32 + (oc >> 1)] = (uint32_t)h0 | ((uint32_t)h1 << 16);
                    lbuf[pos * 32 + (oc >> 1)] = (uint32_t)l0 | ((uint32_t)l1 << 16);
                }
            }
        }
    }

    if (SPLITOUT) {
        __syncthreads();
        for (int i = tid; i < 512; i += NT) {
            int plane = i >> 8;
            int rem = i & 255;
            int pos = rem >> 3, grp = rem & 7;
            int ppy = pos >> 2, ppx = pos & 3;
            int py2 = ty * 8 + ppy, px2 = tx * 4 + ppx;
            if (py2 < PH && px2 < PW) {
                size_t dst = ((((size_t)(b * PH + py2)) * PW + px2) * NOCG + ocg) * 72 +
                             grp * 8;
                const uint32_t* src = (plane ? lbuf : hbuf) + pos * 32 + grp * 4;
                *(uint4*)(outs + (size_t)plane * OPLANE + dst) = *(const uint4*)src;
            }
        }
    }
}

// ---------------- fc: 8 outputs x 8 batches, grid (64,2) = 128 CTAs --------
__global__ void fc_kernel(const float* __restrict__ flat, const float* __restrict__ fcw,
                          const float* __restrict__ fcb, float* __restrict__ g) {
    constexpr int K = 256 * 24 * 24;
    int o0 = blockIdx.x * 8;
    int b0 = blockIdx.y * 8;
    int tid = threadIdx.x;
    float acc[8][8];
#pragma unroll
    for (int b = 0; b < 8; b++)
#pragma unroll
        for (int j = 0; j < 8; j++) acc[b][j] = 0.f;

    const float4* w4[8];
#pragma unroll
    for (int j = 0; j < 8; j++) w4[j] = (const float4*)(fcw + (size_t)(o0 + j) * K);

    for (int k4 = tid; k4 < K / 4; k4 += 256) {
        float4 wv[8];
#pragma unroll
        for (int j = 0; j < 8; j++) wv[j] = w4[j][k4];
#pragma unroll
        for (int b = 0; b < 8; b++) {
            float4 xv = *(const float4*)(flat + (size_t)(b0 + b) * K + (size_t)k4 * 4);
#pragma unroll
            for (int j = 0; j < 8; j++)
                acc[b][j] += wv[j].x * xv.x + wv[j].y * xv.y + wv[j].z * xv.z +
                             wv[j].w * xv.w;
        }
    }
#pragma unroll
    for (int b = 0; b < 8; b++)
#pragma unroll
        for (int j = 0; j < 8; j++)
#pragma unroll
            for (int off = 16; off; off >>= 1)
                acc[b][j] += __shfl_xor_sync(~0u, acc[b][j], off);

    __shared__ float red[8][8][8];
    int wid = tid >> 5, lid = tid & 31;
    if (lid == 0) {
#pragma unroll
        for (int b = 0; b < 8; b++)
#pragma unroll
            for (int j = 0; j < 8; j++) red[wid][b][j] = acc[b][j];
    }
    __syncthreads();
    if (tid < 64) {
        int b = tid >> 3, j = tid & 7;
        float s = fcb[o0 + j];
#pragma unroll
        for (int w = 0; w < 8; w++) s += red[w][b][j];
        g[(b0 + b) * 512 + o0 + j] = s;
    }
}

// ---------------- attention queries q[b,cc] (concat of 3 linears) ----------
__global__ void attq_kernel(const float* __restrict__ g,
                            const float* __restrict__ aw1, const float* __restrict__ ab1,
                            const float* __restrict__ aw2, const float* __restrict__ ab2,
                            const float* __restrict__ aw3, const float* __restrict__ ab3,
                            float* __restrict__ q) {
    int cc = blockIdx.x;
    int b = blockIdx.y;
    int tid = threadIdx.x;
    const float* aw;
    const float* ab;
    int c;
    if (cc < 64) { aw = aw1; ab = ab1; c = cc; }
    else if (cc < 192) { aw = aw2; ab = ab2; c = cc - 64; }
    else { aw = aw3; ab = ab3; c = cc - 192; }

    float s = 0.f;
    for (int k = tid; k < 512; k += 64) s += g[b * 512 + k] * aw[(size_t)c * 512 + k];
#pragma unroll
    for (int off = 16; off; off >>= 1) s += __shfl_xor_sync(~0u, s, off);
    __shared__ float r[2];
    if ((tid & 31) == 0) r[tid >> 5] = s;
    __syncthreads();
    if (tid == 0) q[b * 448 + cc] = r[0] + r[1] + ab[c];
}

// ---------------- merged attention scores (all 3 scales, one launch) -------
__global__ void att_scores_all(const float* __restrict__ f1, const float* __restrict__ f2,
                               const float* __restrict__ f3, const float* __restrict__ q,
                               float* __restrict__ s1, float* __restrict__ s2,
                               float* __restrict__ s3) {
    __shared__ float qs[256];
    int bx = blockIdx.x;
    int b = blockIdx.y;
    int tid = threadIdx.x;
    const float* f;
    float* s;
    int C, N, qoff, nb;
    if (bx < 46) { f = f1; s = s1; C = 64; N = 11664; qoff = 0; nb = bx; }
    else if (bx < 57) { f = f2; s = s2; C = 128; N = 2704; qoff = 64; nb = bx - 46; }
    else { f = f3; s = s3; C = 256; N = 576; qoff = 192; nb = bx - 57; }

    for (int i = tid; i < C; i += 256) qs[i] = q[b * 448 + qoff + i];
    __syncthreads();
    int n = nb * 256 + tid;
    if (n >= N) return;
    float acc = 0.f;
    for (int c = 0; c < C; c++) acc += f[((size_t)b * C + c) * N + n] * qs[c];
    s[(size_t)b * N + n] = acc;
}

// ---------------- merged softmax (48 CTAs = 3 scales x 16 batches) ---------
__global__ void att_reduce_all(float* __restrict__ s1, float* __restrict__ s2,
                               float* __restrict__ s3, float* __restrict__ md) {
    int sc = blockIdx.x >> 4;
    int b = blockIdx.x & 15;
    int tid = threadIdx.x;
    float* s;
    int N;
    if (sc == 0) { s = s1; N = 11664; }
    else if (sc == 1) { s = s2; N = 2704; }
    else { s = s3; N = 576; }

    __shared__ float sm[32];
    __shared__ float bcast;

    float mx = -1e30f;
    for (int n = tid; n < N; n += 1024) mx = fmaxf(mx, s[(size_t)b * N + n]);
#pragma unroll
    for (int off = 16; off; off >>= 1) mx = fmaxf(mx, __shfl_xor_sync(~0u, mx, off));
    if ((tid & 31) == 0) sm[tid >> 5] = mx;
    __syncthreads();
    if (tid < 32) {
        float v = sm[tid];
#pragma unroll
        for (int off = 16; off; off >>= 1) v = fmaxf(v, __shfl_xor_sync(~0u, v, off));
        if (tid == 0) bcast = v;
    }
    __syncthreads();
    float M = bcast;

    float sum = 0.f;
    for (int n = tid; n < N; n += 1024) {
        float e = expf(s[(size_t)b * N + n] - M);
        s[(size_t)b * N + n] = e;
        sum += e;
    }
#pragma unroll
    for (int off = 16; off; off >>= 1) sum += __shfl_xor_sync(~0u, sum, off);
    if ((tid & 31) == 0) sm[tid >> 5] = sum;
    __syncthreads();
    if (tid == 0) {
        float t = 0.f;
        for (int w = 0; w < 32; w++) t += sm[w];
        md[sc * 32 + b] = M;
        md[sc * 32 + 16 + b] = t;
    }
}

// ---------------- merged weighted sum (112 CTAs x 16 batches) --------------
__global__ void att_out_all(const float* __restrict__ f1, const float* __restrict__ f2,
                            const float* __restrict__ f3, const float* __restrict__ e1,
                            const float* __restrict__ e2, const float* __restrict__ e3,
                            const float* __restrict__ md, float* __restrict__ out) {
    int bx = blockIdx.x;
    int b = blockIdx.y;
    int tid = threadIdx.x;
    const float* f;
    const float* e;
    int C, N, off, c0, sc;
    if (bx < 16) { f = f1; e = e1; C = 64; N = 11664; off = 0; c0 = bx * 4; sc = 0; }
    else if (bx < 48) { f = f2; e = e2; C = 128; N = 2704; off = 64; c0 = (bx - 16) * 4; sc = 1; }
    else { f = f3; e = e3; C = 256; N = 576; off = 192; c0 = (bx - 48) * 4; sc = 2; }

    const float* er = e + (size_t)b * N;
    const float* fr = f + ((size_t)b * C + c0) * N;
    float acc[4] = {0.f, 0.f, 0.f, 0.f};
    for (int n = tid; n < N; n += 256) {
        float ev = er[n];
#pragma unroll
        for (int j = 0; j < 4; j++) acc[j] += fr[(size_t)j * N + n] * ev;
    }
#pragma unroll
    for (int j = 0; j < 4; j++)
#pragma unroll
        for (int o = 16; o; o >>= 1) acc[j] += __shfl_xor_sync(~0u, acc[j], o);
    __shared__ float sm[8][4];
    if ((tid & 31) == 0) {
#pragma unroll
        for (int j = 0; j < 4; j++) sm[tid >> 5][j] = acc[j];
    }
    __syncthreads();
    if (tid < 4) {
        float t = 0.f;
#pragma unroll
        for (int w = 0; w < 8; w++) t += sm[w][tid];
        out[b * 448 + off + c0 + tid] = t / md[sc * 32 + 16 + b];
    }
}

// ---------------- launch ----------------------------------------------------
extern "C" void kernel_launch(void* const* d_in, const int* in_sizes, int n_in,
                              void* d_out, int out_size) {
    const float* x = (const float*)d_in[0];
    const float* w1 = (const float*)d_in[1];
    const float* b1 = (const float*)d_in[2];
    const float* w2 = (const float*)d_in[3];
    const float* b2 = (const float*)d_in[4];
    const float* w3 = (const float*)d_in[5];
    const float* b3 = (const float*)d_in[6];
    const float* fcw = (const float*)d_in[7];
    const float* fcb = (const float*)d_in[8];
    const float* aw1 = (const float*)d_in[9];
    const float* ab1 = (const float*)d_in[10];
    const float* aw2 = (const float*)d_in[11];
    const float* ab2 = (const float*)d_in[12];
    const float* aw3 = (const float*)d_in[13];
    const float* ab3 = (const float*)d_in[14];
    float* out = (float*)d_out;

    float *o1, *o2, *o3, *gg, *qq, *s1b, *s2b, *s3b, *md;
    unsigned short *B2, *B3, *o1s, *o2s;
    cudaGetSymbolAddress((void**)&o1, g_o1);
    cudaGetSymbolAddress((void**)&o2, g_o2);
    cudaGetSymbolAddress((void**)&o3, g_o3);
    cudaGetSymbolAddress((void**)&gg, g_g);
    cudaGetSymbolAddress((void**)&qq, g_q);
    cudaGetSymbolAddress((void**)&s1b, g_s1a);
    cudaGetSymbolAddress((void**)&s2b, g_s2a);
    cudaGetSymbolAddress((void**)&s3b, g_s3a);
    cudaGetSymbolAddress((void**)&md, g_md);
    cudaGetSymbolAddress((void**)&B2, g_B2);
    cudaGetSymbolAddress((void**)&B3, g_B3);
    cudaGetSymbolAddress((void**)&o1s, g_o1s);
    cudaGetSymbolAddress((void**)&o2s, g_o2s);

    const size_t PLANE1 = (size_t)16 * 108 * 108 * 72;
    const size_t PLANE2 = (size_t)16 * 52 * 52 * 2 * 72;

    const int SMEM = 69120 + 36864 + 256;
    cudaFuncSetAttribute((const void*)conv_mma_kernel<64, 128, 108, 108, true>,
                         cudaFuncAttributeMaxDynamicSharedMemorySize, SMEM);
    cudaFuncSetAttribute((const void*)conv_mma_kernel<128, 256, 52, 52, false>,
                         cudaFuncAttributeMaxDynamicSharedMemorySize, SMEM);

    prepB_kernel<<<(25 * 128 * 64 + 255) / 256, 256>>>(w2, B2, 64, 128);
    prepB_kernel<<<(50 * 256 * 64 + 255) / 256, 256>>>(w3, B3, 128, 256);

    conv1_kernel<<<dim3(7, 7, 16), 256>>>(x, w1, b1, o1, o1s, PLANE1);
    // conv2 writes fp32 NCHW o2 AND pre-split NHWC o2s (convert2 fused away)
    conv_mma_kernel<64, 128, 108, 108, true><<<dim3(13, 7, 32), 256, SMEM>>>(
        o1s, PLANE1, B2, b2, o2, o2s, PLANE2);
    conv_mma_kernel<128, 256, 52, 52, false><<<dim3(6, 3, 64), 256, SMEM>>>(
        o2s, PLANE2, B3, b3, o3, nullptr, 0);

    fc_kernel<<<dim3(64, 2), 256>>>(o3, fcw, fcb, gg);
    attq_kernel<<<dim3(448, 16), 64>>>(gg, aw1, ab1, aw2, ab2, aw3, ab3, qq);

    // merged attention: all 3 scales concurrent within each launch
    att_scores_all<<<dim3(60, 16), 256>>>(o1, o2, o3, qq, s1b, s2b, s3b);
    att_reduce_all<<<48, 1024>>>(s1b, s2b, s3b, md);
    att_out_all<<<dim3(112, 16), 256>>>(o1, o2, o3, s1b, s2b, s3b, md, out);
}